// round 6
// baseline (speedup 1.0000x reference)
#include <cuda_runtime.h>
#include <math.h>
#include <stdint.h>

#define B_ 8
#define N_ 2048
#define H_ 1024
#define E_ 8
#define D_ 2048
#define T_ 16384   // B_*N_
#define TPAD_ (T_ + 1024)

// ---------------- scratch (device-side referenced ONLY from device code) ----------------
__device__ int   g_expert_idx[T_];
__device__ int   g_counts[E_];
__device__ int   g_offsets[E_ + 1];
__device__ int   g_poffsets[E_ + 1];
__device__ int   g_cursor[E_];
__device__ int   g_ptok[TPAD_];
__device__ float g_prob_sum[E_];
__device__ float g_entropy_sum;
__device__ volatile int g_flag;
__device__ float g_Hbuf[(size_t)TPAD_ * D_];    // GELU activations (tf32-rounded), padded rows

// ---------------- helpers ----------------
__device__ __forceinline__ uint32_t smem_u32(const void* p) {
    uint32_t a;
    asm("{ .reg .u64 t; cvta.to.shared.u64 t, %1; cvt.u32.u64 %0, t; }" : "=r"(a) : "l"(p));
    return a;
}
__device__ __forceinline__ uint32_t tf32_bits(float x) {   // RNA round to tf32
    uint32_t u;
    asm("cvt.rna.tf32.f32 %0, %1;" : "=r"(u) : "f"(x));
    return u;
}
__device__ __forceinline__ void cp_async16(uint32_t dst, const void* src) {
    asm volatile("cp.async.cg.shared.global [%0], [%1], 16;" :: "r"(dst), "l"(src));
}
__device__ __forceinline__ void cp_async16z(uint32_t dst, const void* src, uint32_t sz) {
    asm volatile("cp.async.cg.shared.global [%0], [%1], 16, %2;" :: "r"(dst), "l"(src), "r"(sz));
}
#define CP_COMMIT() asm volatile("cp.async.commit_group;" ::: "memory")
#define CP_WAIT1()  asm volatile("cp.async.wait_group 1;" ::: "memory")
#define CP_WAIT0()  asm volatile("cp.async.wait_group 0;" ::: "memory")

__device__ __forceinline__ void mma_tf32_16x8x8(float& d0, float& d1, float& d2, float& d3,
                                                uint32_t a0, uint32_t a1, uint32_t a2, uint32_t a3,
                                                uint32_t b0, uint32_t b1) {
    asm volatile(
        "mma.sync.aligned.m16n8k8.row.col.f32.tf32.tf32.f32 "
        "{%0,%1,%2,%3}, {%4,%5,%6,%7}, {%8,%9}, {%0,%1,%2,%3};"
        : "+f"(d0), "+f"(d1), "+f"(d2), "+f"(d3)
        : "r"(a0), "r"(a1), "r"(a2), "r"(a3), "r"(b0), "r"(b1));
}

// ---------------- init ----------------
__global__ void init_kernel() {
    int i = blockIdx.x * blockDim.x + threadIdx.x;
    if (i < E_) { g_counts[i] = 0; g_prob_sum[i] = 0.f; }
    if (i == 0) { g_entropy_sum = 0.f; g_flag = 0; }
    for (int p = i; p < TPAD_; p += gridDim.x * blockDim.x) g_ptok[p] = -1;
}

// ---------------- router ----------------
__global__ void router_kernel(const float* __restrict__ x,
                              const float* __restrict__ Wr,
                              const float* __restrict__ br) {
    __shared__ float sWr[H_ * E_];
    for (int i = threadIdx.x; i < H_ * E_; i += blockDim.x) sWr[i] = Wr[i];
    __syncthreads();

    int warp = threadIdx.x >> 5;
    int lane = threadIdx.x & 31;
    int t = blockIdx.x * 8 + warp;
    if (t >= T_) return;

    const float* xr = x + (size_t)t * H_;
    float acc[E_];
#pragma unroll
    for (int e = 0; e < E_; e++) acc[e] = 0.f;
    for (int h = lane; h < H_; h += 32) {
        float xv = xr[h];
        const float* w = &sWr[h * E_];
#pragma unroll
        for (int e = 0; e < E_; e++) acc[e] += xv * w[e];
    }
#pragma unroll
    for (int e = 0; e < E_; e++) {
#pragma unroll
        for (int o = 16; o > 0; o >>= 1)
            acc[e] += __shfl_xor_sync(0xffffffffu, acc[e], o);
    }
    if (lane == 0) {
        float lg[E_];
        float mx = -1e30f;
        int arg = 0;
#pragma unroll
        for (int e = 0; e < E_; e++) {
            lg[e] = acc[e] + br[e];
            if (lg[e] > mx) { mx = lg[e]; arg = e; }
        }
        float s = 0.f;
#pragma unroll
        for (int e = 0; e < E_; e++) { lg[e] = expf(lg[e] - mx); s += lg[e]; }
        float inv = 1.f / s;
        float ent = 0.f;
#pragma unroll
        for (int e = 0; e < E_; e++) {
            float p = lg[e] * inv;
            atomicAdd(&g_prob_sum[e], p);
            ent -= p * logf(p + 1e-8f);
        }
        atomicAdd(&g_entropy_sum, ent);
        atomicAdd(&g_counts[arg], 1);
        g_expert_idx[t] = arg;
    }
}

// ---------------- scan + scatter ----------------
__global__ void scanscatter_kernel() {
    const int t = blockIdx.x * blockDim.x + threadIdx.x;
    if (t == 0) {
        int o = 0, po = 0;
        for (int e = 0; e < E_; e++) {
            g_offsets[e] = o;
            g_cursor[e] = o;
            g_poffsets[e] = po;
            o += g_counts[e];
            po += (g_counts[e] + 127) & ~127;
        }
        g_offsets[E_] = o;
        g_poffsets[E_] = po;
        __threadfence();
        g_flag = 1;
    } else {
        while (g_flag == 0) __nanosleep(64);
    }
    __threadfence();
    if (t < T_) {
        int e = g_expert_idx[t];
        int pos = atomicAdd(&g_cursor[e], 1);
        int p = g_poffsets[e] + (pos - g_offsets[e]);
        g_ptok[p] = t;
    }
}

// ---------------- mma.sync tf32 grouped GEMM: 512 threads, 16 warps ----------------
// Block tile 128(M) x 256(N), K_CHUNK=32, 3-stage cp.async pipeline.
// Warp grid 2(M) x 8(N); warp tile 64x32 = 4 m-frags x 4 n-frags of m16n8k8.
// 4 warps/SMSP -> tensor-pipe latency hiding (R5 had 2 -> tensor stuck at 50%).
// A SMEM [128][36] k-contig; B SMEM [32][264] n-contig.
// ACVT: round A frags to tf32 after LDS (x is raw fp32). Hbuf is stored
// pre-rounded by GEMM1's epilogue, so GEMM2 skips A cvts.
#define STAGES   3
#define KC       32
#define PADK     36
#define PADN     264
#define A_F      (128 * PADK)             // 4608 floats
#define B_F      (KC * PADN)              // 8448 floats
#define STAGE_F  (A_F + B_F)              // 13056 floats
#define GEMM_SMEM (STAGES * STAGE_F * 4)  // 156672 bytes

template<int KTOT, int NTOT, bool GELU>
__global__ void __launch_bounds__(512, 1)
moe_gemm(const float* __restrict__ xin,    // x (token gather for GELU; residual for !GELU)
         const float* __restrict__ W,      // W1/W2: [E][KTOT][NTOT], N contiguous
         const float* __restrict__ bias,
         float* __restrict__ outp)
{
    constexpr int CCH = KTOT / KC;
    const int e = blockIdx.z;
    const int pbase = g_poffsets[e];
    const int pcount = g_poffsets[e + 1] - pbase;
    const int m0 = blockIdx.y * 128;
    if (m0 >= pcount) return;
    const int n0 = blockIdx.x * 256;

    extern __shared__ float sm[];
    const uint32_t smbase = smem_u32(sm);

    const int tid = threadIdx.x;
    const int wid = tid >> 5;      // 0..15
    const int lane = tid & 31;
    const int grp = lane >> 2;     // 0..7
    const int qid = lane & 3;      // 0..3
    const int mrow = (wid & 1) * 64;
    const int nrow = (wid >> 1) * 32;

    // A: 2 slots x 16B per thread; slot idx 0..1023: row = idx>>3, chunk = idx&7
    const char* aptr[2];
    uint32_t aoff[2], asz[2];
#pragma unroll
    for (int i = 0; i < 2; i++) {
        int idx = tid + i * 512;
        int row = idx >> 3, c = idx & 7;
        if (GELU) {
            int tok = g_ptok[pbase + m0 + row];
            aptr[i] = reinterpret_cast<const char*>(
                          xin + (size_t)(tok < 0 ? 0 : tok) * KTOT) + c * 16;
            asz[i] = (tok < 0) ? 0u : 16u;
        } else {
            aptr[i] = reinterpret_cast<const char*>(
                          g_Hbuf + (size_t)(pbase + m0 + row) * KTOT) + c * 16;
            asz[i] = 16u;
        }
        aoff[i] = (uint32_t)(row * PADK + c * 4) * 4;
    }
    // B: 4 slots x 16B; slot idx 0..2047: k-row = idx>>6, n-chunk = idx&63
    const char* bptr[4];
    uint32_t boff[4];
#pragma unroll
    for (int i = 0; i < 4; i++) {
        int idx = tid + i * 512;
        int kr = idx >> 6, c = idx & 63;
        bptr[i] = reinterpret_cast<const char*>(
                      W + (size_t)e * KTOT * NTOT + (size_t)kr * NTOT + n0) + c * 16;
        boff[i] = (uint32_t)(A_F + kr * PADN + c * 4) * 4;
    }

#define LOAD_STAGE(st, ch) do {                                                          \
        uint32_t _sb = smbase + (uint32_t)(st) * (STAGE_F * 4);                          \
        size_t _ga = (size_t)(ch) * (KC * 4);                                            \
        size_t _gb = (size_t)(ch) * ((size_t)KC * NTOT * 4);                             \
        _Pragma("unroll")                                                                \
        for (int _i = 0; _i < 2; _i++) cp_async16z(_sb + aoff[_i], aptr[_i] + _ga, asz[_i]); \
        _Pragma("unroll")                                                                \
        for (int _i = 0; _i < 4; _i++) cp_async16(_sb + boff[_i], bptr[_i] + _gb);       \
    } while (0)

    float acc[4][4][4];
#pragma unroll
    for (int i = 0; i < 4; i++)
#pragma unroll
        for (int j = 0; j < 4; j++)
#pragma unroll
            for (int q = 0; q < 4; q++) acc[i][j][q] = 0.f;

    LOAD_STAGE(0, 0); CP_COMMIT();
    LOAD_STAGE(1, 1); CP_COMMIT();

    for (int c = 0; c < CCH; c++) {
        CP_WAIT1();
        __syncthreads();
        if (c + 2 < CCH) LOAD_STAGE((c + 2) % STAGES, c + 2);
        CP_COMMIT();

        const float* As = sm + (c % STAGES) * STAGE_F;
        const float* Bs = As + A_F;

#pragma unroll
        for (int ks = 0; ks < 4; ks++) {
            const int k0 = ks * 8;
            uint32_t a[4][4], b[4][2];
#pragma unroll
            for (int fm = 0; fm < 4; fm++) {
                const int r = mrow + fm * 16 + grp;
                if (GELU) {   // x is raw fp32 -> round fragments (unbiased RNA)
                    a[fm][0] = tf32_bits(As[r * PADK + k0 + qid]);
                    a[fm][1] = tf32_bits(As[(r + 8) * PADK + k0 + qid]);
                    a[fm][2] = tf32_bits(As[r * PADK + k0 + qid + 4]);
                    a[fm][3] = tf32_bits(As[(r + 8) * PADK + k0 + qid + 4]);
                } else {      // Hbuf pre-rounded to tf32 -> reinterpret only
                    a[fm][0] = __float_as_uint(As[r * PADK + k0 + qid]);
                    a[fm][1] = __float_as_uint(As[(r + 8) * PADK + k0 + qid]);
                    a[fm][2] = __float_as_uint(As[r * PADK + k0 + qid + 4]);
                    a[fm][3] = __float_as_uint(As[(r + 8) * PADK + k0 + qid + 4]);
                }
            }
#pragma unroll
            for (int fn = 0; fn < 4; fn++) {
                const int n = nrow + fn * 8 + grp;
                b[fn][0] = tf32_bits(Bs[(k0 + qid) * PADN + n]);
                b[fn][1] = tf32_bits(Bs[(k0 + qid + 4) * PADN + n]);
            }
#pragma unroll
            for (int fm = 0; fm < 4; fm++)
#pragma unroll
                for (int fn = 0; fn < 4; fn++)
                    mma_tf32_16x8x8(acc[fm][fn][0], acc[fm][fn][1],
                                    acc[fm][fn][2], acc[fm][fn][3],
                                    a[fm][0], a[fm][1], a[fm][2], a[fm][3],
                                    b[fn][0], b[fn][1]);
        }
    }
    CP_WAIT0();

    // ---- epilogue ----
    int toks[4][2];
    if (!GELU) {
#pragma unroll
        for (int fm = 0; fm < 4; fm++) {
            toks[fm][0] = g_ptok[pbase + m0 + mrow + fm * 16 + grp];
            toks[fm][1] = g_ptok[pbase + m0 + mrow + fm * 16 + grp + 8];
        }
    }

#pragma unroll
    for (int fn = 0; fn < 4; fn++) {
        const int col = n0 + nrow + fn * 8 + qid * 2;
        const float2 bv = *reinterpret_cast<const float2*>(bias + (size_t)e * NTOT + col);
#pragma unroll
        for (int fm = 0; fm < 4; fm++) {
#pragma unroll
            for (int h = 0; h < 2; h++) {
                float v0 = acc[fm][fn][h * 2 + 0] + bv.x;
                float v1 = acc[fm][fn][h * 2 + 1] + bv.y;
                if (GELU) {
                    const int prow = pbase + m0 + mrow + fm * 16 + grp + h * 8;
                    v0 = 0.5f * v0 * (1.0f + erff(v0 * 0.7071067811865476f));
                    v1 = 0.5f * v1 * (1.0f + erff(v1 * 0.7071067811865476f));
                    // store pre-rounded tf32 so GEMM2 skips A cvts
                    *reinterpret_cast<float2*>(g_Hbuf + (size_t)prow * NTOT + col) =
                        make_float2(__uint_as_float(tf32_bits(v0)),
                                    __uint_as_float(tf32_bits(v1)));
                } else {
                    const int tok = toks[fm][h];
                    if (tok >= 0) {
                        const float2 xr = *reinterpret_cast<const float2*>(
                            xin + (size_t)tok * NTOT + col);
                        *reinterpret_cast<float2*>(outp + (size_t)tok * NTOT + col) =
                            make_float2(v0 + xr.x, v1 + xr.y);
                    }
                }
            }
        }
    }
#undef LOAD_STAGE
}

// ---------------- losses ----------------
__global__ void finalize_kernel(float* __restrict__ out, int out_size) {
    if (threadIdx.x == 0) {
        long long base = (long long)T_ * H_;
        if ((long long)out_size >= base + 2) {
            float s = 0.f;
            for (int e = 0; e < E_; e++) {
                float p = g_prob_sum[e] / (float)T_;
                s += p * p;
            }
            out[base] = (float)E_ * s;
            out[base + 1] = g_entropy_sum / (float)T_;
        }
        if ((long long)out_size >= base + 2 + E_) {
            for (int e = 0; e < E_; e++)
                out[base + 2 + e] = (float)g_counts[e];
        }
    }
}

// ---------------- launch ----------------
extern "C" void kernel_launch(void* const* d_in, const int* in_sizes, int n_in,
                              void* d_out, int out_size) {
    const float* x  = (const float*)d_in[0];
    const float* Wr = (const float*)d_in[1];
    const float* br = (const float*)d_in[2];
    const float* W1 = (const float*)d_in[3];
    const float* b1 = (const float*)d_in[4];
    const float* W2 = (const float*)d_in[5];
    const float* b2 = (const float*)d_in[6];
    float* out = (float*)d_out;

    cudaFuncSetAttribute(moe_gemm<H_, D_, true>,
                         cudaFuncAttributeMaxDynamicSharedMemorySize, GEMM_SMEM);
    cudaFuncSetAttribute(moe_gemm<D_, H_, false>,
                         cudaFuncAttributeMaxDynamicSharedMemorySize, GEMM_SMEM);

    init_kernel<<<68, 256>>>();
    router_kernel<<<T_ / 8, 256>>>(x, Wr, br);
    scanscatter_kernel<<<T_ / 256, 256>>>();
    moe_gemm<H_, D_, true ><<<dim3(D_ / 256, T_ / 128, E_), 512, GEMM_SMEM>>>(x, W1, b1, out);
    moe_gemm<D_, H_, false><<<dim3(H_ / 256, T_ / 128, E_), 512, GEMM_SMEM>>>(x, W2, b2, out);
    finalize_kernel<<<1, 32>>>(out, out_size);
}